// round 1
// baseline (speedup 1.0000x reference)
#include <cuda_runtime.h>

namespace {
constexpr int NT = 64, NR = 4, DK = 2, KU = 8, BR = 16;
constexpr int FK = BR * KU;        // 128 (f,k) pairs
constexpr int NRHS = DK * KU;      // 16 RHS columns
constexpr int THREADS = 256;
constexpr int CH_STRIDE = NT * NR * BR * 2 * KU;   // 65536 floats / batch
constexpr int NU = 2 * NR * DK * KU * BR;          // 2048
constexpr int PRED_STRIDE = NU + DK * DK * KU * BR; // 2560
constexpr int A_LD = 66;           // padded leading dim for 64x64 matrix

constexpr int SM_HHU = 2 * FK * NT;   // 16384 float2  (HHU[d][j][t])
constexpr int SM_A   = 64 * A_LD;     // 4224 float2
constexpr int SM_RHS = 64 * NRHS;     // 1024 float2
constexpr int SM_U   = NR * DK * FK;  // 1024 float2
constexpr size_t SMEM_BYTES = (size_t)(SM_HHU + SM_A + SM_RHS + SM_U) * 8 + (size_t)FK * 4 * 4;
}

__global__ void __launch_bounds__(THREADS, 1)
uw2v_kernel(const float* __restrict__ channel,
            const float* __restrict__ pred,
            float2* __restrict__ out)
{
    extern __shared__ float2 sm[];
    float2* hhu  = sm;                        // [2][FK][64]
    float2* A    = hhu + SM_HHU;              // [64][A_LD]
    float2* rhs  = A + SM_A;                  // [64][NRHS]
    float2* u_sm = rhs + SM_RHS;              // [NR*DK][FK]
    float*  w_sm = reinterpret_cast<float*>(u_sm + SM_U); // [FK][4] : w[de] per j

    __shared__ float  red[64];
    __shared__ float2 wpart[8];
    __shared__ float2 s_trU;
    __shared__ float  s_scale;
    __shared__ int    s_piv;

    const int b   = blockIdx.x;
    const int tid = threadIdx.x;
    const float* ch = channel + (size_t)b * CH_STRIDE;
    const float* pr = pred    + (size_t)b * PRED_STRIDE;

    // ---------------- Phase 0: load U and W into smem ----------------
    // U reshape: (Nr, dk, Br, 2K); u_sm[(r*2+d)*FK + (f*8+k)] = complex
    for (int idx = tid; idx < NR * DK * FK; idx += THREADS) {
        int j  = idx & (FK - 1);
        int rd = idx >> 7;
        int f = j >> 3, k = j & 7;
        int base = (rd * 16 + f) * 16 + k;
        u_sm[idx] = make_float2(pr[base], pr[base + 8]);
    }
    // W reshape: (dk, dk, Br, K); w_sm[j*4 + (d*2+e)]
    for (int idx = tid; idx < FK * 4; idx += THREADS) {
        int j = idx >> 2, de = idx & 3;
        int f = j >> 3, k = j & 7;
        w_sm[idx] = pr[NU + (de * 16 + f) * 8 + k];
    }
    __syncthreads();

    // ---------------- tr_UWU = 0.1 * sum_{r,d,e,f,k} U W conj(U) ----------------
    float trre = 0.f, trim = 0.f;
    for (int idx = tid; idx < NR * FK; idx += THREADS) {
        int r = idx >> 7, j = idx & (FK - 1);
        float2 u0 = u_sm[(r * 2 + 0) * FK + j];
        float2 u1 = u_sm[(r * 2 + 1) * FK + j];
        float w00 = w_sm[j*4+0], w01 = w_sm[j*4+1], w10 = w_sm[j*4+2], w11 = w_sm[j*4+3];
        float cr = u0.x*u1.x + u0.y*u1.y;   // Re(u0 conj(u1))
        float ci = u0.y*u1.x - u0.x*u1.y;   // Im(u0 conj(u1))
        trre += w00*(u0.x*u0.x + u0.y*u0.y) + w11*(u1.x*u1.x + u1.y*u1.y) + (w01 + w10)*cr;
        trim += (w01 - w10) * ci;
    }
    #pragma unroll
    for (int o = 16; o; o >>= 1) {
        trre += __shfl_down_sync(0xffffffffu, trre, o);
        trim += __shfl_down_sync(0xffffffffu, trim, o);
    }
    if ((tid & 31) == 0) wpart[tid >> 5] = make_float2(trre, trim);
    __syncthreads();
    if (tid == 0) {
        float sx = 0.f, sy = 0.f;
        #pragma unroll
        for (int i = 0; i < 8; i++) { sx += wpart[i].x; sy += wpart[i].y; }
        s_trU = make_float2(0.1f * sx, 0.1f * sy);
    }

    // ---------------- Phase 1: HHU[t,d,j] = sum_r conj(H[t,r,j]) * U[r,d,j] ----------------
    // stored as hhu[(d*FK + j)*64 + t]
    for (int idx = tid; idx < NT * FK; idx += THREADS) {
        int t = idx >> 7, j = idx & (FK - 1);
        int f = j >> 3, k = j & 7;
        float2 a0 = make_float2(0.f, 0.f), a1 = make_float2(0.f, 0.f);
        int hbase = t * 1024 + f * 16 + k;
        #pragma unroll
        for (int r = 0; r < NR; r++) {
            float hre = ch[hbase + r * 256];
            float him = ch[hbase + r * 256 + 8];
            float2 u0 = u_sm[(r * 2 + 0) * FK + j];
            float2 u1 = u_sm[(r * 2 + 1) * FK + j];
            a0.x += hre * u0.x + him * u0.y;
            a0.y += hre * u0.y - him * u0.x;
            a1.x += hre * u1.x + him * u1.y;
            a1.y += hre * u1.y - him * u1.x;
        }
        hhu[j * 64 + t]        = a0;
        hhu[(FK + j) * 64 + t] = a1;
    }
    __syncthreads();

    // ---------------- Phase 2: quad[t,s] = sum_j HHU[t,:,j] W_j conj(HHU[s,:,j]) ----------------
    {
        const int ty = tid >> 4, tx = tid & 15;
        const int t0 = ty * 4, s0 = tx * 4;
        float2 acc[4][4];
        #pragma unroll
        for (int i = 0; i < 4; i++)
            #pragma unroll
            for (int s = 0; s < 4; s++) acc[i][s] = make_float2(0.f, 0.f);

        for (int j = 0; j < FK; j++) {
            float4 wv = reinterpret_cast<const float4*>(w_sm)[j]; // w00,w01,w10,w11
            const float2* r0 = hhu + j * 64;
            const float2* r1 = hhu + (FK + j) * 64;
            float4 pa = *reinterpret_cast<const float4*>(r0 + t0);
            float4 pb = *reinterpret_cast<const float4*>(r0 + t0 + 2);
            float4 qa = *reinterpret_cast<const float4*>(r1 + t0);
            float4 qb = *reinterpret_cast<const float4*>(r1 + t0 + 2);
            float2 a0[4] = { {pa.x,pa.y},{pa.z,pa.w},{pb.x,pb.y},{pb.z,pb.w} };
            float2 a1[4] = { {qa.x,qa.y},{qa.z,qa.w},{qb.x,qb.y},{qb.z,qb.w} };
            float4 sa = *reinterpret_cast<const float4*>(r0 + s0);
            float4 sb = *reinterpret_cast<const float4*>(r0 + s0 + 2);
            float4 ua = *reinterpret_cast<const float4*>(r1 + s0);
            float4 ub = *reinterpret_cast<const float4*>(r1 + s0 + 2);
            float2 b0[4] = { {sa.x,sa.y},{sa.z,sa.w},{sb.x,sb.y},{sb.z,sb.w} };
            float2 b1[4] = { {ua.x,ua.y},{ua.z,ua.w},{ub.x,ub.y},{ub.z,ub.w} };
            float2 c0[4], c1[4];
            #pragma unroll
            for (int s = 0; s < 4; s++) {
                c0[s].x =   wv.x * b0[s].x + wv.y * b1[s].x;
                c0[s].y = -(wv.x * b0[s].y + wv.y * b1[s].y);
                c1[s].x =   wv.z * b0[s].x + wv.w * b1[s].x;
                c1[s].y = -(wv.z * b0[s].y + wv.w * b1[s].y);
            }
            #pragma unroll
            for (int i = 0; i < 4; i++)
                #pragma unroll
                for (int s = 0; s < 4; s++) {
                    acc[i][s].x += a0[i].x*c0[s].x - a0[i].y*c0[s].y
                                 + a1[i].x*c1[s].x - a1[i].y*c1[s].y;
                    acc[i][s].y += a0[i].x*c0[s].y + a0[i].y*c0[s].x
                                 + a1[i].x*c1[s].y + a1[i].y*c1[s].x;
                }
        }
        float2 trU = s_trU;
        #pragma unroll
        for (int i = 0; i < 4; i++)
            #pragma unroll
            for (int s = 0; s < 4; s++) {
                float2 v = acc[i][s];
                if (t0 + i == s0 + s) { v.x += trU.x; v.y += trU.y; }
                A[(t0 + i) * A_LD + (s0 + s)] = v;
            }
    }

    // ---------------- Phase 3: rhs[t, e*8+k] = sum_{d,f} HHU[t,d,f,k] W[d,e,f,k] ----------------
    for (int idx = tid; idx < 64 * NRHS; idx += THREADS) {
        int t = idx >> 4, c = idx & 15;
        int e = c >> 3, k = c & 7;
        float sx = 0.f, sy = 0.f;
        #pragma unroll
        for (int f = 0; f < BR; f++) {
            int j = f * 8 + k;
            float2 x0 = hhu[j * 64 + t];
            float2 x1 = hhu[(FK + j) * 64 + t];
            float wd0 = w_sm[j * 4 + e];
            float wd1 = w_sm[j * 4 + 2 + e];
            sx += x0.x * wd0 + x1.x * wd1;
            sy += x0.y * wd0 + x1.y * wd1;
        }
        rhs[idx] = make_float2(sx, sy);
    }
    __syncthreads();

    // ---------------- Phase 4: Gauss-Jordan with partial pivoting: A X = rhs ----------------
    for (int i = 0; i < 64; i++) {
        // pivot search on column i
        if (tid < 64) {
            float m = -1.f;
            if (tid >= i) { float2 a = A[tid * A_LD + i]; m = fabsf(a.x) + fabsf(a.y); }
            red[tid] = m;
        }
        __syncthreads();
        if (tid < 32) {
            float m = red[tid]; int pi = tid;
            float m2 = red[tid + 32]; if (m2 > m) { m = m2; pi = tid + 32; }
            #pragma unroll
            for (int o = 16; o; o >>= 1) {
                float om = __shfl_down_sync(0xffffffffu, m, o);
                int   op = __shfl_down_sync(0xffffffffu, pi, o);
                if (om > m) { m = om; pi = op; }
            }
            if (tid == 0) s_piv = pi;
        }
        __syncthreads();
        int piv = s_piv;
        if (piv != i) {
            for (int j = tid; j < 64 + NRHS; j += THREADS) {
                if (j < 64) {
                    if (j >= i) {
                        float2 tmp = A[i * A_LD + j];
                        A[i * A_LD + j] = A[piv * A_LD + j];
                        A[piv * A_LD + j] = tmp;
                    }
                } else {
                    int c = j - 64;
                    float2 tmp = rhs[i * NRHS + c];
                    rhs[i * NRHS + c] = rhs[piv * NRHS + c];
                    rhs[piv * NRHS + c] = tmp;
                }
            }
            __syncthreads();
        }
        // normalize pivot row
        {
            float2 d = A[i * A_LD + i];
            float inv = 1.f / (d.x * d.x + d.y * d.y);
            float2 pinv = make_float2(d.x * inv, -d.y * inv);
            for (int j = tid; j < 64 + NRHS; j += THREADS) {
                if (j < 64) {
                    if (j > i) {
                        float2 a = A[i * A_LD + j];
                        A[i * A_LD + j] = make_float2(a.x * pinv.x - a.y * pinv.y,
                                                      a.x * pinv.y + a.y * pinv.x);
                    }
                } else {
                    int c = j - 64;
                    float2 a = rhs[i * NRHS + c];
                    rhs[i * NRHS + c] = make_float2(a.x * pinv.x - a.y * pinv.y,
                                                    a.x * pinv.y + a.y * pinv.x);
                }
            }
        }
        __syncthreads();
        // eliminate column i from all other rows
        {
            int r  = tid >> 2;   // 0..63
            int cg = tid & 3;    // 0..3
            if (r != i) {
                float2 f = A[r * A_LD + i];
                for (int j = i + 1 + cg; j < 64; j += 4) {
                    float2 p = A[i * A_LD + j];
                    float2 a = A[r * A_LD + j];
                    a.x -= f.x * p.x - f.y * p.y;
                    a.y -= f.x * p.y + f.y * p.x;
                    A[r * A_LD + j] = a;
                }
                for (int c = cg; c < NRHS; c += 4) {
                    float2 p = rhs[i * NRHS + c];
                    float2 a = rhs[r * NRHS + c];
                    a.x -= f.x * p.x - f.y * p.y;
                    a.y -= f.x * p.y + f.y * p.x;
                    rhs[r * NRHS + c] = a;
                }
            }
        }
        __syncthreads();
    }

    // ---------------- Phase 5: normalize + write out ----------------
    float ss = 0.f;
    for (int idx = tid; idx < 64 * NRHS; idx += THREADS) {
        float2 v = rhs[idx];
        ss += v.x * v.x + v.y * v.y;
    }
    #pragma unroll
    for (int o = 16; o; o >>= 1) ss += __shfl_down_sync(0xffffffffu, ss, o);
    if ((tid & 31) == 0) red[tid >> 5] = ss;
    __syncthreads();
    if (tid == 0) {
        float tot = 0.f;
        #pragma unroll
        for (int i = 0; i < 8; i++) tot += red[i];
        s_scale = rsqrtf(tot);   // P = 1: total factor is 1/||V0||
    }
    __syncthreads();
    float sc = s_scale;
    float2* op = out + (size_t)b * (64 * NRHS);
    for (int idx = tid; idx < 64 * NRHS; idx += THREADS) {
        float2 v = rhs[idx];
        op[idx] = make_float2(v.x * sc, v.y * sc);
    }
}

extern "C" void kernel_launch(void* const* d_in, const int* in_sizes, int n_in,
                              void* d_out, int out_size)
{
    const float* channel = (const float*)d_in[0];
    const float* pred    = (const float*)d_in[1];
    cudaFuncSetAttribute(uw2v_kernel, cudaFuncAttributeMaxDynamicSharedMemorySize,
                         (int)SMEM_BYTES);
    uw2v_kernel<<<256, THREADS, SMEM_BYTES, 0>>>(channel, pred, (float2*)d_out);
}

// round 2
// speedup vs baseline: 1.2054x; 1.2054x over previous
#include <cuda_runtime.h>

namespace {
constexpr int THREADS = 256;
constexpr int CH_STRIDE = 64 * 4 * 16 * 2 * 8;     // 65536 floats / batch
constexpr int NU = 2 * 4 * 2 * 8 * 16;             // 2048
constexpr int PRED_STRIDE = NU + 2 * 2 * 8 * 16;   // 2560
constexpr int A_LD = 65;
constexpr int NRHS = 16;
constexpr int CH_J = 32;      // j per chunk
constexpr int NCHUNK = 4;

// dynamic smem (floats):
// sA    : 64*65 float2      = 8320 f
// srhs  : 64*16 float2      = 2048 f
// sxre  : [2][32][64]       = 4096 f
// sxim  : 4096 f
// szre  : 4096 f
// szim  : 4096 f
// su    : [8][32] float2    = 512 f
// sw    : [32][4]           = 128 f
constexpr int OFF_A   = 0;
constexpr int OFF_RHS = OFF_A + 64 * A_LD * 2;
constexpr int OFF_XRE = OFF_RHS + 64 * NRHS * 2;
constexpr int OFF_XIM = OFF_XRE + 4096;
constexpr int OFF_ZRE = OFF_XIM + 4096;
constexpr int OFF_ZIM = OFF_ZRE + 4096;
constexpr int OFF_U   = OFF_ZIM + 4096;
constexpr int OFF_W   = OFF_U + 512;
constexpr int SMEM_FLOATS = OFF_W + 128;
constexpr size_t SMEM_BYTES = (size_t)SMEM_FLOATS * 4;

typedef unsigned long long u64t;
}

__device__ __forceinline__ u64t pk2(float x, float y) {
    u64t r; asm("mov.b64 %0,{%1,%2};" : "=l"(r) : "f"(x), "f"(y)); return r;
}
__device__ __forceinline__ void f2fma(u64t& d, u64t a, u64t b) {
    asm("fma.rn.f32x2 %0,%1,%2,%0;" : "+l"(d) : "l"(a), "l"(b));
}
__device__ __forceinline__ float2 up2(u64t v) {
    float2 f; asm("mov.b64 {%0,%1},%2;" : "=f"(f.x), "=f"(f.y) : "l"(v)); return f;
}

__global__ void __launch_bounds__(THREADS, 2)
uw2v_kernel(const float* __restrict__ channel,
            const float* __restrict__ pred,
            float2* __restrict__ out)
{
    extern __shared__ float smf[];
    float2* sA   = (float2*)(smf + OFF_A);
    float2* srhs = (float2*)(smf + OFF_RHS);
    float*  sxre = smf + OFF_XRE;
    float*  sxim = smf + OFF_XIM;
    float*  szre = smf + OFF_ZRE;
    float*  szim = smf + OFF_ZIM;
    float2* su   = (float2*)(smf + OFF_U);
    float*  sw   = smf + OFF_W;

    __shared__ float2 wpart[8];
    __shared__ float2 s_trU;
    __shared__ float2 s_pinv;
    __shared__ float  s_scale;
    __shared__ int    s_piv;

    const int b   = blockIdx.x;
    const int tid = threadIdx.x;
    const float* ch = channel + (size_t)b * CH_STRIDE;
    const float* pr = pred    + (size_t)b * PRED_STRIDE;

    const int ty = tid >> 4, tx = tid & 15;
    const int t0 = ty * 4, s0 = tx * 4;

    // GEMM accumulators: acc[tpair][s] packed f32x2 over (t0+2tp, t0+2tp+1)
    u64t accre[2][4], accim[2][4];
    #pragma unroll
    for (int p = 0; p < 2; p++)
        #pragma unroll
        for (int s = 0; s < 4; s++) { accre[p][s] = 0ull; accim[p][s] = 0ull; }

    float2 rhsacc[4] = {{0,0},{0,0},{0,0},{0,0}};
    float trre = 0.f, trim = 0.f;

    for (int c = 0; c < NCHUNK; c++) {
        // ---- load U chunk, W chunk ----
        {
            int rd = tid >> 5, jj = tid & 31;
            int f = 4 * c + (jj >> 3), k = jj & 7;
            int base = (rd * 16 + f) * 16 + k;
            su[tid] = make_float2(pr[base], pr[base + 8]);
            if (tid < 128) {
                int jw = tid >> 2, de = tid & 3;
                int fw = 4 * c + (jw >> 3), kw = jw & 7;
                sw[tid] = pr[NU + (de * 16 + fw) * 8 + kw];
            }
        }
        __syncthreads();

        // ---- phase 1: X[t,d,jj] = sum_r conj(H) * U ----
        {
            int t = tid & 63;
            int floc = tid >> 6;
            const float* chp = ch + t * 1024 + (4 * c + floc) * 16;
            float xr[2][8], xi[2][8];
            #pragma unroll
            for (int d = 0; d < 2; d++)
                #pragma unroll
                for (int k = 0; k < 8; k++) { xr[d][k] = 0.f; xi[d][k] = 0.f; }
            #pragma unroll
            for (int r = 0; r < 4; r++) {
                float4 h0 = *(const float4*)(chp + r * 256);
                float4 h1 = *(const float4*)(chp + r * 256 + 4);
                float4 g0 = *(const float4*)(chp + r * 256 + 8);
                float4 g1 = *(const float4*)(chp + r * 256 + 12);
                float hre[8] = {h0.x,h0.y,h0.z,h0.w,h1.x,h1.y,h1.z,h1.w};
                float him[8] = {g0.x,g0.y,g0.z,g0.w,g1.x,g1.y,g1.z,g1.w};
                #pragma unroll
                for (int d = 0; d < 2; d++) {
                    const float2* uptr = su + (r * 2 + d) * 32 + floc * 8;
                    #pragma unroll
                    for (int k = 0; k < 8; k++) {
                        float2 u = uptr[k];
                        xr[d][k] += hre[k] * u.x + him[k] * u.y;
                        xi[d][k] += hre[k] * u.y - him[k] * u.x;
                    }
                }
            }
            #pragma unroll
            for (int d = 0; d < 2; d++)
                #pragma unroll
                for (int k = 0; k < 8; k++) {
                    int jj = floc * 8 + k;
                    sxre[d * 2048 + jj * 64 + t] = xr[d][k];
                    sxim[d * 2048 + jj * 64 + t] = xi[d][k];
                }
        }
        // ---- trU accumulate (uses su/sw only) ----
        if (tid < 128) {
            int r = tid >> 5, jj = tid & 31;
            float2 u0 = su[(r * 2) * 32 + jj];
            float2 u1 = su[(r * 2 + 1) * 32 + jj];
            const float* wj = sw + jj * 4;
            float cr = u0.x * u1.x + u0.y * u1.y;
            float ci = u0.y * u1.x - u0.x * u1.y;
            trre += wj[0] * (u0.x*u0.x + u0.y*u0.y) + wj[3] * (u1.x*u1.x + u1.y*u1.y)
                  + (wj[1] + wj[2]) * cr;
            trim += (wj[1] - wj[2]) * ci;
        }
        __syncthreads();

        // ---- Z = W * conj(X), and rhs accumulate ----
        #pragma unroll
        for (int it = 0; it < 16; it++) {
            int idx = tid + 256 * it;             // d*2048 + jj*64 + s
            int d = idx >> 11, jj = (idx >> 6) & 31, s = idx & 63;
            float w0 = sw[jj * 4 + d * 2];
            float w1 = sw[jj * 4 + d * 2 + 1];
            szre[idx] =  w0 * sxre[jj * 64 + s] + w1 * sxre[2048 + jj * 64 + s];
            szim[idx] = -(w0 * sxim[jj * 64 + s] + w1 * sxim[2048 + jj * 64 + s]);
        }
        #pragma unroll
        for (int q = 0; q < 4; q++) {
            int item = tid + 256 * q;
            int t = item >> 4, cc = item & 15, e = cc >> 3, k = cc & 7;
            float sxr = 0.f, sxi = 0.f;
            #pragma unroll
            for (int floc = 0; floc < 4; floc++) {
                int jj = floc * 8 + k;
                float w0 = sw[jj * 4 + e];
                float w1 = sw[jj * 4 + 2 + e];
                sxr += sxre[jj * 64 + t] * w0 + sxre[2048 + jj * 64 + t] * w1;
                sxi += sxim[jj * 64 + t] * w0 + sxim[2048 + jj * 64 + t] * w1;
            }
            rhsacc[q].x += sxr; rhsacc[q].y += sxi;
        }
        __syncthreads();

        // ---- quad GEMM accumulate: acc[t,s] += sum_{d,jj} X[t,d,jj] * Z[d,jj,s] ----
        #pragma unroll 2
        for (int jj = 0; jj < CH_J; jj++) {
            ulonglong2 ar0 = *(const ulonglong2*)(sxre + jj * 64 + t0);
            ulonglong2 ai0 = *(const ulonglong2*)(sxim + jj * 64 + t0);
            ulonglong2 ar1 = *(const ulonglong2*)(sxre + 2048 + jj * 64 + t0);
            ulonglong2 ai1 = *(const ulonglong2*)(sxim + 2048 + jj * 64 + t0);
            float4 zr0 = *(const float4*)(szre + jj * 64 + s0);
            float4 zi0 = *(const float4*)(szim + jj * 64 + s0);
            float4 zr1 = *(const float4*)(szre + 2048 + jj * 64 + s0);
            float4 zi1 = *(const float4*)(szim + 2048 + jj * 64 + s0);
            float zra[4] = {zr0.x, zr0.y, zr0.z, zr0.w};
            float zia[4] = {zi0.x, zi0.y, zi0.z, zi0.w};
            float zrb[4] = {zr1.x, zr1.y, zr1.z, zr1.w};
            float zib[4] = {zi1.x, zi1.y, zi1.z, zi1.w};
            #pragma unroll
            for (int s = 0; s < 4; s++) {
                // d = 0
                {
                    u64t zrp = pk2(zra[s], zra[s]);
                    u64t zip = pk2(zia[s], zia[s]);
                    u64t nzp = pk2(-zia[s], -zia[s]);
                    f2fma(accre[0][s], ar0.x, zrp); f2fma(accre[0][s], ai0.x, nzp);
                    f2fma(accim[0][s], ar0.x, zip); f2fma(accim[0][s], ai0.x, zrp);
                    f2fma(accre[1][s], ar0.y, zrp); f2fma(accre[1][s], ai0.y, nzp);
                    f2fma(accim[1][s], ar0.y, zip); f2fma(accim[1][s], ai0.y, zrp);
                }
                // d = 1
                {
                    u64t zrp = pk2(zrb[s], zrb[s]);
                    u64t zip = pk2(zib[s], zib[s]);
                    u64t nzp = pk2(-zib[s], -zib[s]);
                    f2fma(accre[0][s], ar1.x, zrp); f2fma(accre[0][s], ai1.x, nzp);
                    f2fma(accim[0][s], ar1.x, zip); f2fma(accim[0][s], ai1.x, zrp);
                    f2fma(accre[1][s], ar1.y, zrp); f2fma(accre[1][s], ai1.y, nzp);
                    f2fma(accim[1][s], ar1.y, zip); f2fma(accim[1][s], ai1.y, zrp);
                }
            }
        }
        __syncthreads();   // before next chunk overwrites X/Z
    }

    // ---- trU reduction ----
    #pragma unroll
    for (int o = 16; o; o >>= 1) {
        trre += __shfl_down_sync(0xffffffffu, trre, o);
        trim += __shfl_down_sync(0xffffffffu, trim, o);
    }
    if ((tid & 31) == 0) wpart[tid >> 5] = make_float2(trre, trim);
    __syncthreads();
    if (tid == 0) {
        float sx = 0.f, sy = 0.f;
        #pragma unroll
        for (int i = 0; i < 8; i++) { sx += wpart[i].x; sy += wpart[i].y; }
        s_trU = make_float2(0.1f * sx, 0.1f * sy);
    }
    __syncthreads();

    // ---- write A (acc + trU*I) and rhs ----
    {
        float2 trU = s_trU;
        #pragma unroll
        for (int p = 0; p < 2; p++)
            #pragma unroll
            for (int s = 0; s < 4; s++) {
                float2 re2 = up2(accre[p][s]);
                float2 im2 = up2(accim[p][s]);
                int t = t0 + p * 2;
                int col = s0 + s;
                float2 v0 = make_float2(re2.x, im2.x);
                float2 v1 = make_float2(re2.y, im2.y);
                if (t == col)     { v0.x += trU.x; v0.y += trU.y; }
                if (t + 1 == col) { v1.x += trU.x; v1.y += trU.y; }
                sA[t * A_LD + col]       = v0;
                sA[(t + 1) * A_LD + col] = v1;
            }
        #pragma unroll
        for (int q = 0; q < 4; q++) srhs[tid + 256 * q] = rhsacc[q];
    }
    __syncthreads();

    // ---- Gauss-Jordan with partial pivoting, 3 syncs/iter ----
    for (int i = 0; i < 64; i++) {
        if (tid < 32) {
            float best = -1.f; int bp = i;
            #pragma unroll
            for (int h = 0; h < 2; h++) {
                int r = tid + h * 32;
                if (r >= i) {
                    float2 a = sA[r * A_LD + i];
                    float m = fabsf(a.x) + fabsf(a.y);
                    if (m > best) { best = m; bp = r; }
                }
            }
            #pragma unroll
            for (int o = 16; o; o >>= 1) {
                float ob = __shfl_down_sync(0xffffffffu, best, o);
                int   op = __shfl_down_sync(0xffffffffu, bp, o);
                if (ob > best) { best = ob; bp = op; }
            }
            if (tid == 0) {
                s_piv = bp;
                float2 d = sA[bp * A_LD + i];
                float inv = 1.f / (d.x * d.x + d.y * d.y);
                s_pinv = make_float2(d.x * inv, -d.y * inv);
            }
        }
        __syncthreads();
        const int piv = s_piv;
        const float2 pinv = s_pinv;
        // swap + normalize
        {
            int tot = (64 - i) + NRHS;
            for (int jx = tid; jx < tot; jx += THREADS) {
                if (jx < 64 - i) {
                    int col = i + jx;
                    float2 old_i = sA[i * A_LD + col];
                    float2 pv    = sA[piv * A_LD + col];
                    sA[i * A_LD + col] = make_float2(pv.x * pinv.x - pv.y * pinv.y,
                                                     pv.x * pinv.y + pv.y * pinv.x);
                    if (piv != i) sA[piv * A_LD + col] = old_i;
                } else {
                    int cc = jx - (64 - i);
                    float2 old_i = srhs[i * NRHS + cc];
                    float2 pv    = srhs[piv * NRHS + cc];
                    srhs[i * NRHS + cc] = make_float2(pv.x * pinv.x - pv.y * pinv.y,
                                                      pv.x * pinv.y + pv.y * pinv.x);
                    if (piv != i) srhs[piv * NRHS + cc] = old_i;
                }
            }
        }
        __syncthreads();
        // eliminate
        {
            int r = tid >> 2, cg = tid & 3;
            if (r != i) {
                float2 f = sA[r * A_LD + i];
                for (int col = i + 1 + cg; col < 64; col += 4) {
                    float2 p = sA[i * A_LD + col];
                    float2 a = sA[r * A_LD + col];
                    a.x -= f.x * p.x - f.y * p.y;
                    a.y -= f.x * p.y + f.y * p.x;
                    sA[r * A_LD + col] = a;
                }
                #pragma unroll
                for (int cc = cg; cc < NRHS; cc += 4) {
                    float2 p = srhs[i * NRHS + cc];
                    float2 a = srhs[r * NRHS + cc];
                    a.x -= f.x * p.x - f.y * p.y;
                    a.y -= f.x * p.y + f.y * p.x;
                    srhs[r * NRHS + cc] = a;
                }
            }
        }
        __syncthreads();
    }

    // ---- normalize + write out ----
    float ss = 0.f;
    #pragma unroll
    for (int q = 0; q < 4; q++) {
        float2 v = srhs[tid + 256 * q];
        ss += v.x * v.x + v.y * v.y;
    }
    #pragma unroll
    for (int o = 16; o; o >>= 1) ss += __shfl_down_sync(0xffffffffu, ss, o);
    if ((tid & 31) == 0) wpart[tid >> 5].x = ss;
    __syncthreads();
    if (tid == 0) {
        float tot = 0.f;
        #pragma unroll
        for (int i = 0; i < 8; i++) tot += wpart[i].x;
        s_scale = rsqrtf(tot);
    }
    __syncthreads();
    const float sc = s_scale;
    float2* op = out + (size_t)b * (64 * NRHS);
    #pragma unroll
    for (int q = 0; q < 4; q++) {
        float2 v = srhs[tid + 256 * q];
        op[tid + 256 * q] = make_float2(v.x * sc, v.y * sc);
    }
}

extern "C" void kernel_launch(void* const* d_in, const int* in_sizes, int n_in,
                              void* d_out, int out_size)
{
    const float* channel = (const float*)d_in[0];
    const float* pred    = (const float*)d_in[1];
    cudaFuncSetAttribute(uw2v_kernel, cudaFuncAttributeMaxDynamicSharedMemorySize,
                         (int)SMEM_BYTES);
    uw2v_kernel<<<256, THREADS, SMEM_BYTES, 0>>>(channel, pred, (float2*)d_out);
}